// round 5
// baseline (speedup 1.0000x reference)
#include <cuda_runtime.h>
#include <cuda_bf16.h>
#include <math.h>

// Problem constants
#define B_  4096
#define F_  26
#define E_  64
#define D_  1664          // F_*E_
#define N1  1024
#define N2  512
#define N3  256
#define NCROSS 3

// Scratch (no cudaMalloc allowed)
__device__ float g_x0[B_ * D_];     // gathered embeddings [B, D]
__device__ float g_xdot[B_];        // per-row partial logit: cross(x) . out_w[0:D]
__device__ float g_h1[B_ * N1];
__device__ float g_h2[B_ * N2];
__device__ float g_h3[B_ * N3];

// ---------------------------------------------------------------------------
// Kernel A: fused embedding gather + cross network + head partial dot.
// One block per row. x (cross iterate) lives in registers; it is never
// materialized to global memory because it is only consumed by the output
// head dot product.
// ---------------------------------------------------------------------------
__global__ __launch_bounds__(256) void k_gather_cross(
    const int* __restrict__ ids,         // [B, F]
    const float* __restrict__ emb,       // [H, E]
    const float* __restrict__ cross_w,   // [3, D]
    const float* __restrict__ cross_b,   // [3, D]
    const float* __restrict__ out_w)     // [D+256, 1]
{
    const int b = blockIdx.x;
    const int tid = threadIdx.x;

    __shared__ float sx0[D_];
    __shared__ float sred[8];

    // Gather: x0[b, f*64+e] = emb[ids[b,f], e]
    for (int idx = tid; idx < D_; idx += 256) {
        int f = idx >> 6;            // / 64
        int e = idx & 63;
        int row = ids[b * F_ + f];
        float v = emb[row * E_ + e];
        sx0[idx] = v;
        g_x0[b * D_ + idx] = v;
    }
    __syncthreads();

    // x in registers: 7 slots per thread (D_ = 6*256 + 128)
    float x[7];
#pragma unroll
    for (int j = 0; j < 7; j++) {
        int idx = tid + j * 256;
        x[j] = (idx < D_) ? sx0[idx] : 0.0f;
    }

    for (int i = 0; i < NCROSS; i++) {
        // s = x . cross_w[i]
        float p = 0.0f;
#pragma unroll
        for (int j = 0; j < 7; j++) {
            int idx = tid + j * 256;
            if (idx < D_) p += x[j] * cross_w[i * D_ + idx];
        }
        // block reduce
#pragma unroll
        for (int o = 16; o > 0; o >>= 1) p += __shfl_xor_sync(0xffffffffu, p, o);
        int w = tid >> 5, l = tid & 31;
        if (l == 0) sred[w] = p;
        __syncthreads();
        float s;
        if (w == 0) {
            float v = (l < 8) ? sred[l] : 0.0f;
#pragma unroll
            for (int o = 4; o > 0; o >>= 1) v += __shfl_xor_sync(0xffffffffu, v, o);
            if (l == 0) sred[0] = v;
        }
        __syncthreads();
        s = sred[0];
        __syncthreads();   // sred reused next iteration

        // x = x0 * s + cross_b[i] + x
#pragma unroll
        for (int j = 0; j < 7; j++) {
            int idx = tid + j * 256;
            if (idx < D_) x[j] = sx0[idx] * s + cross_b[i * D_ + idx] + x[j];
        }
    }

    // partial logit: x . out_w[0:D]
    float p = 0.0f;
#pragma unroll
    for (int j = 0; j < 7; j++) {
        int idx = tid + j * 256;
        if (idx < D_) p += x[j] * out_w[idx];
    }
#pragma unroll
    for (int o = 16; o > 0; o >>= 1) p += __shfl_xor_sync(0xffffffffu, p, o);
    int w = tid >> 5, l = tid & 31;
    if (l == 0) sred[w] = p;
    __syncthreads();
    if (w == 0) {
        float v = (l < 8) ? sred[l] : 0.0f;
#pragma unroll
        for (int o = 4; o > 0; o >>= 1) v += __shfl_xor_sync(0xffffffffu, v, o);
        if (l == 0) g_xdot[b] = v;
    }
}

// ---------------------------------------------------------------------------
// Tiled fp32 GEMM with bias + relu: C[M,N] = relu(A[M,K] @ W[K,N] + bias)
// 64x64 block tile, BK=32, 256 threads, 4x4 micro-tile per thread.
// Requires M%64==0, N%64==0, K%32==0 (all shapes here satisfy this).
// ---------------------------------------------------------------------------
#define BM 64
#define BN 64
#define BK 32

__global__ __launch_bounds__(256) void k_gemm_relu(
    const float* __restrict__ A,
    const float* __restrict__ W,
    const float* __restrict__ bias,
    float* __restrict__ C,
    int M, int N, int K)
{
    __shared__ float As[BK][BM];   // transposed: As[k][m]
    __shared__ float Bs[BK][BN];

    const int tid = threadIdx.x;
    const int tx = tid & 15;       // 0..15 -> N
    const int ty = tid >> 4;       // 0..15 -> M
    const int bn0 = blockIdx.x * BN;
    const int bm0 = blockIdx.y * BM;

    float acc[4][4] = {};

    for (int k0 = 0; k0 < K; k0 += BK) {
        // A tile: 64 (m) x 32 (k) = 512 float4 loads, 2 per thread
#pragma unroll
        for (int i = 0; i < 2; i++) {
            int idx = tid + i * 256;         // 0..511
            int m  = idx >> 3;               // 8 float4 per row
            int kk = (idx & 7) << 2;
            float4 v = *(const float4*)&A[(size_t)(bm0 + m) * K + k0 + kk];
            As[kk + 0][m] = v.x;
            As[kk + 1][m] = v.y;
            As[kk + 2][m] = v.z;
            As[kk + 3][m] = v.w;
        }
        // W tile: 32 (k) x 64 (n)
#pragma unroll
        for (int i = 0; i < 2; i++) {
            int idx = tid + i * 256;
            int kk = idx >> 4;               // 16 float4 per row
            int n  = (idx & 15) << 2;
            *(float4*)&Bs[kk][n] = *(const float4*)&W[(size_t)(k0 + kk) * N + bn0 + n];
        }
        __syncthreads();

#pragma unroll
        for (int kk = 0; kk < BK; kk++) {
            float4 a4 = *(const float4*)&As[kk][ty << 2];
            float4 b4 = *(const float4*)&Bs[kk][tx << 2];
            float a[4] = {a4.x, a4.y, a4.z, a4.w};
            float bb[4] = {b4.x, b4.y, b4.z, b4.w};
#pragma unroll
            for (int i = 0; i < 4; i++)
#pragma unroll
                for (int j = 0; j < 4; j++)
                    acc[i][j] += a[i] * bb[j];
        }
        __syncthreads();
    }

#pragma unroll
    for (int i = 0; i < 4; i++) {
        int m = bm0 + (ty << 2) + i;
#pragma unroll
        for (int j = 0; j < 4; j++) {
            int n = bn0 + (tx << 2) + j;
            float v = acc[i][j] + bias[n];
            C[(size_t)m * N + n] = v > 0.0f ? v : 0.0f;
        }
    }
}

// ---------------------------------------------------------------------------
// Head: logit = g_xdot[b] + h3[b] . out_w[D:D+256] + out_b; out = sigmoid
// One warp per row, 8 rows per block to cut launch/scheduling overhead.
// ---------------------------------------------------------------------------
__global__ __launch_bounds__(256) void k_head(
    const float* __restrict__ h3,
    const float* __restrict__ out_w,
    const float* __restrict__ out_b,
    float* __restrict__ out)
{
    const int b = blockIdx.x * 8 + (threadIdx.x >> 5);
    const int l = threadIdx.x & 31;
    float p = 0.0f;
#pragma unroll
    for (int j = 0; j < N3 / 32; j++) {
        int idx = l + j * 32;
        p += h3[b * N3 + idx] * out_w[D_ + idx];
    }
#pragma unroll
    for (int o = 16; o > 0; o >>= 1) p += __shfl_xor_sync(0xffffffffu, p, o);
    if (l == 0) {
        float logit = g_xdot[b] + p + out_b[0];
        out[b] = 1.0f / (1.0f + expf(-logit));
    }
}

// ---------------------------------------------------------------------------
extern "C" void kernel_launch(void* const* d_in, const int* in_sizes, int n_in,
                              void* d_out, int out_size)
{
    const int*   ids     = (const int*)  d_in[0];
    const float* emb     = (const float*)d_in[1];
    const float* cross_w = (const float*)d_in[2];
    const float* cross_b = (const float*)d_in[3];
    const float* w1      = (const float*)d_in[4];
    const float* b1      = (const float*)d_in[5];
    const float* w2      = (const float*)d_in[6];
    const float* b2      = (const float*)d_in[7];
    const float* w3      = (const float*)d_in[8];
    const float* b3      = (const float*)d_in[9];
    const float* out_w   = (const float*)d_in[10];
    const float* out_b   = (const float*)d_in[11];
    float* out = (float*)d_out;

    float* x0; cudaGetSymbolAddress((void**)&x0, g_x0);
    float* h1; cudaGetSymbolAddress((void**)&h1, g_h1);
    float* h2; cudaGetSymbolAddress((void**)&h2, g_h2);
    float* h3; cudaGetSymbolAddress((void**)&h3, g_h3);

    // 1) gather + cross + head partial
    k_gather_cross<<<B_, 256>>>(ids, emb, cross_w, cross_b, out_w);

    // 2) deep tower
    {
        dim3 g(N1 / BN, B_ / BM);
        k_gemm_relu<<<g, 256>>>(x0, w1, b1, h1, B_, N1, D_);
    }
    {
        dim3 g(N2 / BN, B_ / BM);
        k_gemm_relu<<<g, 256>>>(h1, w2, b2, h2, B_, N2, N1);
    }
    {
        dim3 g(N3 / BN, B_ / BM);
        k_gemm_relu<<<g, 256>>>(h2, w3, b3, h3, B_, N3, N2);
    }

    // 3) head
    k_head<<<B_ / 8, 256>>>(h3, out_w, out_b, out);
}

// round 8
// speedup vs baseline: 4.2192x; 4.2192x over previous
#include <cuda_runtime.h>
#include <cuda_bf16.h>
#include <math.h>
#include <cstdint>

// Problem constants
#define B_  4096
#define F_  26
#define E_  64
#define D_  1664          // F_*E_
#define N1  1024
#define N2  512
#define N3  256
#define NCROSS 3

// Scratch (no cudaMalloc allowed)
__device__ __nv_bfloat16 g_x0b[B_ * D_];    // gathered embeddings, bf16 [B, D]
__device__ float        g_xdot[B_];         // cross(x) . out_w[0:D], fp32
__device__ __nv_bfloat16 g_h1b[B_ * N1];
__device__ __nv_bfloat16 g_h2b[B_ * N2];
__device__ __nv_bfloat16 g_h3b[B_ * N3];
__device__ __nv_bfloat16 g_w1t[N1 * D_];    // w1^T bf16 [N][K]
__device__ __nv_bfloat16 g_w2t[N2 * N1];
__device__ __nv_bfloat16 g_w3t[N3 * N2];

// ---------------------------------------------------------------------------
// Weight convert + transpose: fp32 [K][N] -> bf16 [N][K]. Tiled via smem.
// K, N multiples of 32.
// ---------------------------------------------------------------------------
__global__ __launch_bounds__(256) void k_transpose_bf16(
    const float* __restrict__ W, __nv_bfloat16* __restrict__ Wt, int K, int N)
{
    __shared__ float s[32][33];
    const int n0 = blockIdx.x * 32, k0 = blockIdx.y * 32;
    const int tx = threadIdx.x & 31, ty = threadIdx.x >> 5;   // (32, 8)
#pragma unroll
    for (int i = 0; i < 32; i += 8)
        s[ty + i][tx] = W[(size_t)(k0 + ty + i) * N + n0 + tx];
    __syncthreads();
#pragma unroll
    for (int i = 0; i < 32; i += 8)
        Wt[(size_t)(n0 + ty + i) * K + k0 + tx] = __float2bfloat16(s[tx][ty + i]);
}

// ---------------------------------------------------------------------------
// Kernel A: fused embedding gather + cross network + head partial dot.
// One block per row; cross iterate x stays in registers (fp32, exact).
// Emits bf16 x0 for the GEMM tower.
// ---------------------------------------------------------------------------
__global__ __launch_bounds__(256) void k_gather_cross(
    const int* __restrict__ ids,         // [B, F]
    const float* __restrict__ emb,       // [H, E]
    const float* __restrict__ cross_w,   // [3, D]
    const float* __restrict__ cross_b,   // [3, D]
    const float* __restrict__ out_w)     // [D+256, 1]
{
    const int b = blockIdx.x;
    const int tid = threadIdx.x;

    __shared__ float sx0[D_];
    __shared__ float sred[8];

    for (int idx = tid; idx < D_; idx += 256) {
        int f = idx >> 6;
        int e = idx & 63;
        int row = ids[b * F_ + f];
        float v = emb[row * E_ + e];
        sx0[idx] = v;
        g_x0b[b * D_ + idx] = __float2bfloat16(v);
    }
    __syncthreads();

    float x[7];
#pragma unroll
    for (int j = 0; j < 7; j++) {
        int idx = tid + j * 256;
        x[j] = (idx < D_) ? sx0[idx] : 0.0f;
    }

    for (int i = 0; i < NCROSS; i++) {
        float p = 0.0f;
#pragma unroll
        for (int j = 0; j < 7; j++) {
            int idx = tid + j * 256;
            if (idx < D_) p += x[j] * cross_w[i * D_ + idx];
        }
#pragma unroll
        for (int o = 16; o > 0; o >>= 1) p += __shfl_xor_sync(0xffffffffu, p, o);
        int w = tid >> 5, l = tid & 31;
        if (l == 0) sred[w] = p;
        __syncthreads();
        float s;
        if (w == 0) {
            float v = (l < 8) ? sred[l] : 0.0f;
#pragma unroll
            for (int o = 4; o > 0; o >>= 1) v += __shfl_xor_sync(0xffffffffu, v, o);
            if (l == 0) sred[0] = v;
        }
        __syncthreads();
        s = sred[0];
        __syncthreads();

#pragma unroll
        for (int j = 0; j < 7; j++) {
            int idx = tid + j * 256;
            if (idx < D_) x[j] = sx0[idx] * s + cross_b[i * D_ + idx] + x[j];
        }
    }

    float p = 0.0f;
#pragma unroll
    for (int j = 0; j < 7; j++) {
        int idx = tid + j * 256;
        if (idx < D_) p += x[j] * out_w[idx];
    }
#pragma unroll
    for (int o = 16; o > 0; o >>= 1) p += __shfl_xor_sync(0xffffffffu, p, o);
    int w = tid >> 5, l = tid & 31;
    if (l == 0) sred[w] = p;
    __syncthreads();
    if (w == 0) {
        float v = (l < 8) ? sred[l] : 0.0f;
#pragma unroll
        for (int o = 4; o > 0; o >>= 1) v += __shfl_xor_sync(0xffffffffu, v, o);
        if (l == 0) g_xdot[b] = v;
    }
}

// ---------------------------------------------------------------------------
// bf16 tensor-core GEMM + bias + relu:
//   C[M,N] = relu(A[M,K] @ B[K,N] + bias), B given transposed as Bt[N,K].
// BM=128, BN=64, BK=32, 256 threads (8 warps, 4x2), mma.m16n8k16 bf16.
// Requires M%128==0, N%64==0, K%32==0 (all shapes satisfy this).
// Smem row stride 40 bf16 (80B): 16B-aligned rows AND conflict-free frag loads.
// ---------------------------------------------------------------------------
__global__ __launch_bounds__(256) void k_gemm_bf16(
    const __nv_bfloat16* __restrict__ A,   // [M][K]
    const __nv_bfloat16* __restrict__ Bt,  // [N][K]
    const float* __restrict__ bias,        // [N]
    __nv_bfloat16* __restrict__ C,         // [M][N]
    int M, int N, int K)
{
    __shared__ __align__(16) __nv_bfloat16 As[128][40];
    __shared__ __align__(16) __nv_bfloat16 Bs[64][40];

    const int tid  = threadIdx.x;
    const int warp = tid >> 5, lane = tid & 31;
    const int g = lane >> 2, t = lane & 3;
    const int wm = (warp & 3) * 32;     // 4 warps along m
    const int wn = (warp >> 2) * 32;    // 2 warps along n
    const int bm0 = blockIdx.y * 128;
    const int bn0 = blockIdx.x * 64;

    // global load mapping
    const int am  = tid >> 2;           // A rows: tid -> row, tid+256 -> row+64
    const int akp = (tid & 3) * 8;      // 8 bf16 per uint4
    const int bn  = tid >> 2;           // B row (one uint4 per thread)

    float acc[2][4][4];
#pragma unroll
    for (int i = 0; i < 2; i++)
#pragma unroll
        for (int j = 0; j < 4; j++)
#pragma unroll
            for (int c = 0; c < 4; c++) acc[i][j][c] = 0.0f;

    const size_t arow0 = (size_t)(bm0 + am) * K;
    const size_t arow1 = (size_t)(bm0 + am + 64) * K;
    const size_t brow  = (size_t)(bn0 + bn) * K;

    uint4 ra0 = *(const uint4*)&A[arow0 + akp];
    uint4 ra1 = *(const uint4*)&A[arow1 + akp];
    uint4 rb0 = *(const uint4*)&Bt[brow + akp];

    const int niter = K >> 5;
    for (int it = 0; it < niter; it++) {
        *(uint4*)&As[am][akp]      = ra0;
        *(uint4*)&As[am + 64][akp] = ra1;
        *(uint4*)&Bs[bn][akp]      = rb0;
        __syncthreads();

        if (it + 1 < niter) {
            int k0 = (it + 1) << 5;
            ra0 = *(const uint4*)&A[arow0 + k0 + akp];
            ra1 = *(const uint4*)&A[arow1 + k0 + akp];
            rb0 = *(const uint4*)&Bt[brow + k0 + akp];
        }

#pragma unroll
        for (int ks = 0; ks < 32; ks += 16) {
            uint32_t af[2][4], bf[4][2];
#pragma unroll
            for (int mt = 0; mt < 2; mt++) {
                int rm = wm + mt * 16 + g;
                af[mt][0] = *(const uint32_t*)&As[rm][ks + 2 * t];
                af[mt][1] = *(const uint32_t*)&As[rm + 8][ks + 2 * t];
                af[mt][2] = *(const uint32_t*)&As[rm][ks + 2 * t + 8];
                af[mt][3] = *(const uint32_t*)&As[rm + 8][ks + 2 * t + 8];
            }
#pragma unroll
            for (int nt = 0; nt < 4; nt++) {
                int rn = wn + nt * 8 + g;
                bf[nt][0] = *(const uint32_t*)&Bs[rn][ks + 2 * t];
                bf[nt][1] = *(const uint32_t*)&Bs[rn][ks + 2 * t + 8];
            }
#pragma unroll
            for (int mt = 0; mt < 2; mt++)
#pragma unroll
                for (int nt = 0; nt < 4; nt++) {
                    asm volatile(
                        "mma.sync.aligned.m16n8k16.row.col.f32.bf16.bf16.f32 "
                        "{%0,%1,%2,%3}, {%4,%5,%6,%7}, {%8,%9}, {%0,%1,%2,%3};\n"
                        : "+f"(acc[mt][nt][0]), "+f"(acc[mt][nt][1]),
                          "+f"(acc[mt][nt][2]), "+f"(acc[mt][nt][3])
                        : "r"(af[mt][0]), "r"(af[mt][1]), "r"(af[mt][2]), "r"(af[mt][3]),
                          "r"(bf[nt][0]), "r"(bf[nt][1]));
                }
        }
        __syncthreads();
    }

    // Epilogue: bias + relu + bf16 store
#pragma unroll
    for (int mt = 0; mt < 2; mt++) {
        int row0 = bm0 + wm + mt * 16 + g;
#pragma unroll
        for (int nt = 0; nt < 4; nt++) {
            int col = bn0 + wn + nt * 8 + 2 * t;
            float b0v = bias[col], b1v = bias[col + 1];
            float v00 = fmaxf(acc[mt][nt][0] + b0v, 0.0f);
            float v01 = fmaxf(acc[mt][nt][1] + b1v, 0.0f);
            float v10 = fmaxf(acc[mt][nt][2] + b0v, 0.0f);
            float v11 = fmaxf(acc[mt][nt][3] + b1v, 0.0f);
            __nv_bfloat162 p0 = __floats2bfloat162_rn(v00, v01);
            __nv_bfloat162 p1 = __floats2bfloat162_rn(v10, v11);
            *(__nv_bfloat162*)&C[(size_t)row0 * N + col]       = p0;
            *(__nv_bfloat162*)&C[(size_t)(row0 + 8) * N + col] = p1;
        }
    }
}

// ---------------------------------------------------------------------------
// Head: logit = g_xdot[b] + h3[b] . out_w[D:D+256] + out_b; out = sigmoid.
// One warp per row, 8 rows per block.
// ---------------------------------------------------------------------------
__global__ __launch_bounds__(256) void k_head(
    const __nv_bfloat16* __restrict__ h3,
    const float* __restrict__ out_w,
    const float* __restrict__ out_b,
    float* __restrict__ out)
{
    const int b = blockIdx.x * 8 + (threadIdx.x >> 5);
    const int l = threadIdx.x & 31;
    float p = 0.0f;
#pragma unroll
    for (int j = 0; j < N3 / 32; j++) {
        int idx = l + j * 32;
        p += __bfloat162float(h3[b * N3 + idx]) * out_w[D_ + idx];
    }
#pragma unroll
    for (int o = 16; o > 0; o >>= 1) p += __shfl_xor_sync(0xffffffffu, p, o);
    if (l == 0) {
        float logit = g_xdot[b] + p + out_b[0];
        out[b] = 1.0f / (1.0f + expf(-logit));
    }
}

// ---------------------------------------------------------------------------
extern "C" void kernel_launch(void* const* d_in, const int* in_sizes, int n_in,
                              void* d_out, int out_size)
{
    const int*   ids     = (const int*)  d_in[0];
    const float* emb     = (const float*)d_in[1];
    const float* cross_w = (const float*)d_in[2];
    const float* cross_b = (const float*)d_in[3];
    const float* w1      = (const float*)d_in[4];
    const float* b1      = (const float*)d_in[5];
    const float* w2      = (const float*)d_in[6];
    const float* b2      = (const float*)d_in[7];
    const float* w3      = (const float*)d_in[8];
    const float* b3      = (const float*)d_in[9];
    const float* out_w   = (const float*)d_in[10];
    const float* out_b   = (const float*)d_in[11];
    float* out = (float*)d_out;

    __nv_bfloat16 *x0b, *h1b, *h2b, *h3b, *w1t, *w2t, *w3t;
    cudaGetSymbolAddress((void**)&x0b, g_x0b);
    cudaGetSymbolAddress((void**)&h1b, g_h1b);
    cudaGetSymbolAddress((void**)&h2b, g_h2b);
    cudaGetSymbolAddress((void**)&h3b, g_h3b);
    cudaGetSymbolAddress((void**)&w1t, g_w1t);
    cudaGetSymbolAddress((void**)&w2t, g_w2t);
    cudaGetSymbolAddress((void**)&w3t, g_w3t);

    // 0) weight convert+transpose (fp32 [K][N] -> bf16 [N][K])
    k_transpose_bf16<<<dim3(N1 / 32, D_ / 32), 256>>>(w1, w1t, D_, N1);
    k_transpose_bf16<<<dim3(N2 / 32, N1 / 32), 256>>>(w2, w2t, N1, N2);
    k_transpose_bf16<<<dim3(N3 / 32, N2 / 32), 256>>>(w3, w3t, N2, N3);

    // 1) gather + cross + head partial (fp32 exact path)
    k_gather_cross<<<B_, 256>>>(ids, emb, cross_w, cross_b, out_w);

    // 2) deep tower on tensor cores (bf16 in, fp32 accum)
    k_gemm_bf16<<<dim3(N1 / 64, B_ / 128), 256>>>(x0b, w1t, b1, h1b, B_, N1, D_);
    k_gemm_bf16<<<dim3(N2 / 64, B_ / 128), 256>>>(h1b, w2t, b2, h2b, B_, N2, N1);
    k_gemm_bf16<<<dim3(N3 / 64, B_ / 128), 256>>>(h2b, w3t, b3, h3b, B_, N3, N2);

    // 3) head
    k_head<<<B_ / 8, 256>>>(h3b, out_w, out_b, out);
}

// round 9
// speedup vs baseline: 4.4419x; 1.0528x over previous
#include <cuda_runtime.h>
#include <cuda_bf16.h>
#include <math.h>
#include <cstdint>

// Problem constants
#define B_  4096
#define F_  26
#define E_  64
#define D_  1664          // F_*E_
#define NV4 (D_ / 4)      // 416 float4 groups per row
#define N1  1024
#define N2  512
#define N3  256

// Scratch (no cudaMalloc allowed)
__device__ __nv_bfloat16 g_x0b[B_ * D_];    // gathered embeddings, bf16 [B, D]
__device__ float        g_xdot[B_];         // cross(x) . out_w[0:D], fp32
__device__ float        g_tconst[3];        // t1, t2, u (bias-derived scalars)
__device__ __nv_bfloat16 g_h1b[B_ * N1];
__device__ __nv_bfloat16 g_h2b[B_ * N2];
__device__ __nv_bfloat16 g_h3b[B_ * N3];
__device__ __nv_bfloat16 g_w1t[N1 * D_];    // w1^T bf16 [N][K]
__device__ __nv_bfloat16 g_w2t[N2 * N1];
__device__ __nv_bfloat16 g_w3t[N3 * N2];

// ---------------------------------------------------------------------------
// Constant scalars of the collapsed cross net (data-independent):
//   t1 = cb0 . w1
//   t2 = (cb0+cb1) . w2
//   u  = (cb0+cb1+cb2) . out_w[0:D]
// One block.
// ---------------------------------------------------------------------------
__global__ __launch_bounds__(256) void k_const(
    const float* __restrict__ cross_w,   // [3, D]
    const float* __restrict__ cross_b,   // [3, D]
    const float* __restrict__ out_w)     // [D+256]
{
    __shared__ float sred[3][8];
    const int tid = threadIdx.x;
    float a1 = 0.f, a2 = 0.f, a3 = 0.f;
    for (int d = tid; d < D_; d += 256) {
        float c0 = cross_b[d];
        float c01 = c0 + cross_b[D_ + d];
        float c012 = c01 + cross_b[2 * D_ + d];
        a1 += c0  * cross_w[D_ + d];
        a2 += c01 * cross_w[2 * D_ + d];
        a3 += c012 * out_w[d];
    }
#pragma unroll
    for (int o = 16; o > 0; o >>= 1) {
        a1 += __shfl_xor_sync(0xffffffffu, a1, o);
        a2 += __shfl_xor_sync(0xffffffffu, a2, o);
        a3 += __shfl_xor_sync(0xffffffffu, a3, o);
    }
    int w = tid >> 5, l = tid & 31;
    if (l == 0) { sred[0][w] = a1; sred[1][w] = a2; sred[2][w] = a3; }
    __syncthreads();
    if (tid < 3) {
        float v = 0.f;
#pragma unroll
        for (int j = 0; j < 8; j++) v += sred[tid][j];
        g_tconst[tid] = v;
    }
}

// ---------------------------------------------------------------------------
// Fused gather + collapsed cross + head partial.
// One block per row. Single pass over the row:
//   - gather emb -> bf16 x0 (8B packed stores)
//   - q0..q2 = x0 . cross_w[i],  q3 = x0 . out_w[0:D]
// Then a 10-flop scalar recurrence yields xdot (identical math to the
// iterative cross net; see derivation x_i = a_i*x0 + prefix(cross_b)).
// ---------------------------------------------------------------------------
__global__ __launch_bounds__(256) void k_gather_cross(
    const int* __restrict__ ids,         // [B, F]
    const float* __restrict__ emb,       // [H, E]
    const float* __restrict__ cross_w,   // [3, D]
    const float* __restrict__ out_w)     // [D+256]
{
    const int b = blockIdx.x;
    const int tid = threadIdx.x;

    __shared__ int sid[F_];
    __shared__ float sred[4][8];

    if (tid < F_) sid[tid] = ids[b * F_ + tid];
    __syncthreads();

    float q0 = 0.f, q1 = 0.f, q2 = 0.f, q3 = 0.f;

    // 416 float4 groups, 256 threads: iter0 = 256 groups, iter1 = 160.
    for (int v4 = tid; v4 < NV4; v4 += 256) {
        int f = v4 >> 4;                 // field (16 float4 per field)
        int e4 = (v4 & 15) << 2;         // element offset within field
        int row = sid[f];
        float4 v = *(const float4*)&emb[(size_t)row * E_ + e4];

        int d = v4 << 2;
        float4 w0 = *(const float4*)&cross_w[d];
        float4 w1 = *(const float4*)&cross_w[D_ + d];
        float4 w2 = *(const float4*)&cross_w[2 * D_ + d];
        float4 wo = *(const float4*)&out_w[d];

        q0 += v.x * w0.x + v.y * w0.y + v.z * w0.z + v.w * w0.w;
        q1 += v.x * w1.x + v.y * w1.y + v.z * w1.z + v.w * w1.w;
        q2 += v.x * w2.x + v.y * w2.y + v.z * w2.z + v.w * w2.w;
        q3 += v.x * wo.x + v.y * wo.y + v.z * wo.z + v.w * wo.w;

        // packed bf16 store (8 bytes)
        __nv_bfloat162 p0 = __floats2bfloat162_rn(v.x, v.y);
        __nv_bfloat162 p1 = __floats2bfloat162_rn(v.z, v.w);
        uint2 pk;
        pk.x = *(uint32_t*)&p0;
        pk.y = *(uint32_t*)&p1;
        *(uint2*)&g_x0b[(size_t)b * D_ + d] = pk;
    }

#pragma unroll
    for (int o = 16; o > 0; o >>= 1) {
        q0 += __shfl_xor_sync(0xffffffffu, q0, o);
        q1 += __shfl_xor_sync(0xffffffffu, q1, o);
        q2 += __shfl_xor_sync(0xffffffffu, q2, o);
        q3 += __shfl_xor_sync(0xffffffffu, q3, o);
    }
    int w = tid >> 5, l = tid & 31;
    if (l == 0) { sred[0][w] = q0; sred[1][w] = q1; sred[2][w] = q2; sred[3][w] = q3; }
    __syncthreads();
    if (tid == 0) {
        float r0 = 0.f, r1 = 0.f, r2 = 0.f, r3 = 0.f;
#pragma unroll
        for (int j = 0; j < 8; j++) {
            r0 += sred[0][j]; r1 += sred[1][j]; r2 += sred[2][j]; r3 += sred[3][j];
        }
        float t1 = g_tconst[0], t2 = g_tconst[1], u = g_tconst[2];
        float s0 = r0;                    // t0 = 0
        float a1 = 1.0f + s0;
        float s1 = a1 * r1 + t1;
        float a2 = a1 + s1;
        float s2 = a2 * r2 + t2;
        float a3 = a2 + s2;
        g_xdot[b] = a3 * r3 + u;
    }
}

// ---------------------------------------------------------------------------
// Weight convert + transpose: fp32 [K][N] -> bf16 [N][K]. Tiled via smem.
// ---------------------------------------------------------------------------
__global__ __launch_bounds__(256) void k_transpose_bf16(
    const float* __restrict__ W, __nv_bfloat16* __restrict__ Wt, int K, int N)
{
    __shared__ float s[32][33];
    const int n0 = blockIdx.x * 32, k0 = blockIdx.y * 32;
    const int tx = threadIdx.x & 31, ty = threadIdx.x >> 5;   // (32, 8)
#pragma unroll
    for (int i = 0; i < 32; i += 8)
        s[ty + i][tx] = W[(size_t)(k0 + ty + i) * N + n0 + tx];
    __syncthreads();
#pragma unroll
    for (int i = 0; i < 32; i += 8)
        Wt[(size_t)(n0 + ty + i) * K + k0 + tx] = __float2bfloat16(s[tx][ty + i]);
}

// ---------------------------------------------------------------------------
// bf16 tensor-core GEMM + bias + relu:
//   C[M,N] = relu(A[M,K] @ B[K,N] + bias), B given transposed as Bt[N,K].
// BM=128, BN=64, BK=32, 256 threads (8 warps, 4x2), mma.m16n8k16 bf16.
// ---------------------------------------------------------------------------
__global__ __launch_bounds__(256) void k_gemm_bf16(
    const __nv_bfloat16* __restrict__ A,   // [M][K]
    const __nv_bfloat16* __restrict__ Bt,  // [N][K]
    const float* __restrict__ bias,        // [N]
    __nv_bfloat16* __restrict__ C,         // [M][N]
    int M, int N, int K)
{
    __shared__ __align__(16) __nv_bfloat16 As[128][40];
    __shared__ __align__(16) __nv_bfloat16 Bs[64][40];

    const int tid  = threadIdx.x;
    const int warp = tid >> 5, lane = tid & 31;
    const int g = lane >> 2, t = lane & 3;
    const int wm = (warp & 3) * 32;
    const int wn = (warp >> 2) * 32;
    const int bm0 = blockIdx.y * 128;
    const int bn0 = blockIdx.x * 64;

    const int am  = tid >> 2;
    const int akp = (tid & 3) * 8;
    const int bn  = tid >> 2;

    float acc[2][4][4];
#pragma unroll
    for (int i = 0; i < 2; i++)
#pragma unroll
        for (int j = 0; j < 4; j++)
#pragma unroll
            for (int c = 0; c < 4; c++) acc[i][j][c] = 0.0f;

    const size_t arow0 = (size_t)(bm0 + am) * K;
    const size_t arow1 = (size_t)(bm0 + am + 64) * K;
    const size_t brow  = (size_t)(bn0 + bn) * K;

    uint4 ra0 = *(const uint4*)&A[arow0 + akp];
    uint4 ra1 = *(const uint4*)&A[arow1 + akp];
    uint4 rb0 = *(const uint4*)&Bt[brow + akp];

    const int niter = K >> 5;
    for (int it = 0; it < niter; it++) {
        *(uint4*)&As[am][akp]      = ra0;
        *(uint4*)&As[am + 64][akp] = ra1;
        *(uint4*)&Bs[bn][akp]      = rb0;
        __syncthreads();

        if (it + 1 < niter) {
            int k0 = (it + 1) << 5;
            ra0 = *(const uint4*)&A[arow0 + k0 + akp];
            ra1 = *(const uint4*)&A[arow1 + k0 + akp];
            rb0 = *(const uint4*)&Bt[brow + k0 + akp];
        }

#pragma unroll
        for (int ks = 0; ks < 32; ks += 16) {
            uint32_t af[2][4], bf[4][2];
#pragma unroll
            for (int mt = 0; mt < 2; mt++) {
                int rm = wm + mt * 16 + g;
                af[mt][0] = *(const uint32_t*)&As[rm][ks + 2 * t];
                af[mt][1] = *(const uint32_t*)&As[rm + 8][ks + 2 * t];
                af[mt][2] = *(const uint32_t*)&As[rm][ks + 2 * t + 8];
                af[mt][3] = *(const uint32_t*)&As[rm + 8][ks + 2 * t + 8];
            }
#pragma unroll
            for (int nt = 0; nt < 4; nt++) {
                int rn = wn + nt * 8 + g;
                bf[nt][0] = *(const uint32_t*)&Bs[rn][ks + 2 * t];
                bf[nt][1] = *(const uint32_t*)&Bs[rn][ks + 2 * t + 8];
            }
#pragma unroll
            for (int mt = 0; mt < 2; mt++)
#pragma unroll
                for (int nt = 0; nt < 4; nt++) {
                    asm volatile(
                        "mma.sync.aligned.m16n8k16.row.col.f32.bf16.bf16.f32 "
                        "{%0,%1,%2,%3}, {%4,%5,%6,%7}, {%8,%9}, {%0,%1,%2,%3};\n"
                        : "+f"(acc[mt][nt][0]), "+f"(acc[mt][nt][1]),
                          "+f"(acc[mt][nt][2]), "+f"(acc[mt][nt][3])
                        : "r"(af[mt][0]), "r"(af[mt][1]), "r"(af[mt][2]), "r"(af[mt][3]),
                          "r"(bf[nt][0]), "r"(bf[nt][1]));
                }
        }
        __syncthreads();
    }

#pragma unroll
    for (int mt = 0; mt < 2; mt++) {
        int row0 = bm0 + wm + mt * 16 + g;
#pragma unroll
        for (int nt = 0; nt < 4; nt++) {
            int col = bn0 + wn + nt * 8 + 2 * t;
            float b0v = bias[col], b1v = bias[col + 1];
            float v00 = fmaxf(acc[mt][nt][0] + b0v, 0.0f);
            float v01 = fmaxf(acc[mt][nt][1] + b1v, 0.0f);
            float v10 = fmaxf(acc[mt][nt][2] + b0v, 0.0f);
            float v11 = fmaxf(acc[mt][nt][3] + b1v, 0.0f);
            __nv_bfloat162 p0 = __floats2bfloat162_rn(v00, v01);
            __nv_bfloat162 p1 = __floats2bfloat162_rn(v10, v11);
            *(__nv_bfloat162*)&C[(size_t)row0 * N + col]       = p0;
            *(__nv_bfloat162*)&C[(size_t)(row0 + 8) * N + col] = p1;
        }
    }
}

// ---------------------------------------------------------------------------
// Head: logit = g_xdot[b] + h3[b] . out_w[D:D+256] + out_b; out = sigmoid.
// ---------------------------------------------------------------------------
__global__ __launch_bounds__(256) void k_head(
    const __nv_bfloat16* __restrict__ h3,
    const float* __restrict__ out_w,
    const float* __restrict__ out_b,
    float* __restrict__ out)
{
    const int b = blockIdx.x * 8 + (threadIdx.x >> 5);
    const int l = threadIdx.x & 31;
    float p = 0.0f;
#pragma unroll
    for (int j = 0; j < N3 / 32; j++) {
        int idx = l + j * 32;
        p += __bfloat162float(h3[b * N3 + idx]) * out_w[D_ + idx];
    }
#pragma unroll
    for (int o = 16; o > 0; o >>= 1) p += __shfl_xor_sync(0xffffffffu, p, o);
    if (l == 0) {
        float logit = g_xdot[b] + p + out_b[0];
        out[b] = 1.0f / (1.0f + expf(-logit));
    }
}

// ---------------------------------------------------------------------------
extern "C" void kernel_launch(void* const* d_in, const int* in_sizes, int n_in,
                              void* d_out, int out_size)
{
    const int*   ids     = (const int*)  d_in[0];
    const float* emb     = (const float*)d_in[1];
    const float* cross_w = (const float*)d_in[2];
    const float* cross_b = (const float*)d_in[3];
    const float* w1      = (const float*)d_in[4];
    const float* b1      = (const float*)d_in[5];
    const float* w2      = (const float*)d_in[6];
    const float* b2      = (const float*)d_in[7];
    const float* w3      = (const float*)d_in[8];
    const float* b3      = (const float*)d_in[9];
    const float* out_w   = (const float*)d_in[10];
    const float* out_b   = (const float*)d_in[11];
    float* out = (float*)d_out;

    __nv_bfloat16 *x0b, *h1b, *h2b, *h3b, *w1t, *w2t, *w3t;
    cudaGetSymbolAddress((void**)&x0b, g_x0b);
    cudaGetSymbolAddress((void**)&h1b, g_h1b);
    cudaGetSymbolAddress((void**)&h2b, g_h2b);
    cudaGetSymbolAddress((void**)&h3b, g_h3b);
    cudaGetSymbolAddress((void**)&w1t, g_w1t);
    cudaGetSymbolAddress((void**)&w2t, g_w2t);
    cudaGetSymbolAddress((void**)&w3t, g_w3t);

    // 0) bias-derived constants + weight convert/transpose
    k_const<<<1, 256>>>(cross_w, cross_b, out_w);
    k_transpose_bf16<<<dim3(N1 / 32, D_ / 32), 256>>>(w1, w1t, D_, N1);
    k_transpose_bf16<<<dim3(N2 / 32, N1 / 32), 256>>>(w2, w2t, N1, N2);
    k_transpose_bf16<<<dim3(N3 / 32, N2 / 32), 256>>>(w3, w3t, N2, N3);

    // 1) fused gather + collapsed cross (fp32 exact path)
    k_gather_cross<<<B_, 256>>>(ids, emb, cross_w, out_w);

    // 2) deep tower on tensor cores (bf16 in, fp32 accum)
    k_gemm_bf16<<<dim3(N1 / 64, B_ / 128), 256>>>(x0b, w1t, b1, h1b, B_, N1, D_);
    k_gemm_bf16<<<dim3(N2 / 64, B_ / 128), 256>>>(h1b, w2t, b2, h2b, B_, N2, N1);
    k_gemm_bf16<<<dim3(N3 / 64, B_ / 128), 256>>>(h2b, w3t, b3, h3b, B_, N3, N2);

    // 3) head
    k_head<<<B_ / 8, 256>>>(h3b, out_w, out_b, out);
}

// round 10
// speedup vs baseline: 5.4393x; 1.2245x over previous
#include <cuda_runtime.h>
#include <cuda_bf16.h>
#include <math.h>
#include <cstdint>

// Problem constants
#define B_  4096
#define F_  26
#define E_  64
#define D_  1664          // F_*E_
#define NV4 (D_ / 4)      // 416 float4 groups per row
#define N1  1024
#define N2  512
#define N3  256

// Scratch (no cudaMalloc allowed)
__device__ __nv_bfloat16 g_x0b[B_ * D_];
__device__ float        g_xdot[B_];
__device__ float        g_tconst[3];
__device__ __nv_bfloat16 g_h1b[B_ * N1];
__device__ __nv_bfloat16 g_h2b[B_ * N2];
__device__ __nv_bfloat16 g_h3b[B_ * N3];
__device__ __nv_bfloat16 g_w1t[N1 * D_];
__device__ __nv_bfloat16 g_w2t[N2 * N1];
__device__ __nv_bfloat16 g_w3t[N3 * N2];

__device__ __forceinline__ uint32_t smem_u32(const void* p) {
    return (uint32_t)__cvta_generic_to_shared(p);
}
#define CP16(dst, src) \
    asm volatile("cp.async.ca.shared.global [%0], [%1], 16;\n" :: "r"(dst), "l"(src))
#define CP_COMMIT() asm volatile("cp.async.commit_group;\n")

// ---------------------------------------------------------------------------
// One launch: all three weight transposes (fp32 [K][N] -> bf16 [N][K]) plus
// the bias-derived constant scalars of the collapsed cross net.
//   tiles: w1 1664 tiles, w2 512, w3 128; block 2304 computes constants.
// ---------------------------------------------------------------------------
#define T1_TILES ((N1/32)*(D_/32))             // 1664
#define T2_TILES ((N2/32)*(N1/32))             // 512
#define T3_TILES ((N3/32)*(N2/32))             // 128
#define PREP_BLOCKS (T1_TILES + T2_TILES + T3_TILES + 1)

__global__ __launch_bounds__(256) void k_prep(
    const float* __restrict__ w1, const float* __restrict__ w2,
    const float* __restrict__ w3,
    __nv_bfloat16* __restrict__ w1t, __nv_bfloat16* __restrict__ w2t,
    __nv_bfloat16* __restrict__ w3t,
    const float* __restrict__ cross_w, const float* __restrict__ cross_b,
    const float* __restrict__ out_w)
{
    const int bid = blockIdx.x;
    const int tid = threadIdx.x;

    if (bid == T1_TILES + T2_TILES + T3_TILES) {
        // constants: t1 = cb0.w1c, t2 = (cb0+cb1).w2c, u = (cb0+cb1+cb2).out_w
        __shared__ float sred[3][8];
        float a1 = 0.f, a2 = 0.f, a3 = 0.f;
        for (int d = tid; d < D_; d += 256) {
            float c0 = cross_b[d];
            float c01 = c0 + cross_b[D_ + d];
            float c012 = c01 + cross_b[2 * D_ + d];
            a1 += c0   * cross_w[D_ + d];
            a2 += c01  * cross_w[2 * D_ + d];
            a3 += c012 * out_w[d];
        }
#pragma unroll
        for (int o = 16; o > 0; o >>= 1) {
            a1 += __shfl_xor_sync(0xffffffffu, a1, o);
            a2 += __shfl_xor_sync(0xffffffffu, a2, o);
            a3 += __shfl_xor_sync(0xffffffffu, a3, o);
        }
        int w = tid >> 5, l = tid & 31;
        if (l == 0) { sred[0][w] = a1; sred[1][w] = a2; sred[2][w] = a3; }
        __syncthreads();
        if (tid < 3) {
            float v = 0.f;
#pragma unroll
            for (int j = 0; j < 8; j++) v += sred[tid][j];
            g_tconst[tid] = v;
        }
        return;
    }

    const float* W; __nv_bfloat16* Wt; int K, N, tile;
    if (bid < T1_TILES)                 { W = w1; Wt = w1t; K = D_; N = N1; tile = bid; }
    else if (bid < T1_TILES + T2_TILES) { W = w2; Wt = w2t; K = N1; N = N2; tile = bid - T1_TILES; }
    else                                { W = w3; Wt = w3t; K = N2; N = N3; tile = bid - T1_TILES - T2_TILES; }

    __shared__ float s[32][33];
    const int tilesN = N / 32;
    const int n0 = (tile % tilesN) * 32, k0 = (tile / tilesN) * 32;
    const int tx = tid & 31, ty = tid >> 5;
#pragma unroll
    for (int i = 0; i < 32; i += 8)
        s[ty + i][tx] = W[(size_t)(k0 + ty + i) * N + n0 + tx];
    __syncthreads();
#pragma unroll
    for (int i = 0; i < 32; i += 8)
        Wt[(size_t)(n0 + ty + i) * K + k0 + tx] = __float2bfloat16(s[tx][ty + i]);
}

// ---------------------------------------------------------------------------
// Fused gather + collapsed cross + head partial. 2 rows per block: the four
// weight vectors (cross_w x3, out_w) are read once and applied to both rows.
// ---------------------------------------------------------------------------
#define RPB 2
__global__ __launch_bounds__(256) void k_gather_cross(
    const int* __restrict__ ids,
    const float* __restrict__ emb,
    const float* __restrict__ cross_w,
    const float* __restrict__ out_w)
{
    const int b0 = blockIdx.x * RPB;
    const int tid = threadIdx.x;

    __shared__ int sid[RPB][F_];
    __shared__ float sred[RPB][4][8];

    if (tid < RPB * F_) {
        int r = tid / F_, f = tid % F_;
        sid[r][f] = ids[(b0 + r) * F_ + f];
    }
    __syncthreads();

    float q[RPB][4];
#pragma unroll
    for (int r = 0; r < RPB; r++)
#pragma unroll
        for (int c = 0; c < 4; c++) q[r][c] = 0.f;

    for (int v4 = tid; v4 < NV4; v4 += 256) {
        int f = v4 >> 4;
        int e4 = (v4 & 15) << 2;
        int d = v4 << 2;

        float4 w0 = *(const float4*)&cross_w[d];
        float4 w1 = *(const float4*)&cross_w[D_ + d];
        float4 w2 = *(const float4*)&cross_w[2 * D_ + d];
        float4 wo = *(const float4*)&out_w[d];

#pragma unroll
        for (int r = 0; r < RPB; r++) {
            int row = sid[r][f];
            float4 v = *(const float4*)&emb[(size_t)row * E_ + e4];
            q[r][0] += v.x * w0.x + v.y * w0.y + v.z * w0.z + v.w * w0.w;
            q[r][1] += v.x * w1.x + v.y * w1.y + v.z * w1.z + v.w * w1.w;
            q[r][2] += v.x * w2.x + v.y * w2.y + v.z * w2.z + v.w * w2.w;
            q[r][3] += v.x * wo.x + v.y * wo.y + v.z * wo.z + v.w * wo.w;

            __nv_bfloat162 p0 = __floats2bfloat162_rn(v.x, v.y);
            __nv_bfloat162 p1 = __floats2bfloat162_rn(v.z, v.w);
            uint2 pk;
            pk.x = *(uint32_t*)&p0;
            pk.y = *(uint32_t*)&p1;
            *(uint2*)&g_x0b[(size_t)(b0 + r) * D_ + d] = pk;
        }
    }

#pragma unroll
    for (int r = 0; r < RPB; r++)
#pragma unroll
        for (int c = 0; c < 4; c++)
#pragma unroll
            for (int o = 16; o > 0; o >>= 1)
                q[r][c] += __shfl_xor_sync(0xffffffffu, q[r][c], o);

    int w = tid >> 5, l = tid & 31;
    if (l == 0)
#pragma unroll
        for (int r = 0; r < RPB; r++)
#pragma unroll
            for (int c = 0; c < 4; c++) sred[r][c][w] = q[r][c];
    __syncthreads();
    if (tid < RPB) {
        int r = tid;
        float rr[4];
#pragma unroll
        for (int c = 0; c < 4; c++) {
            float v = 0.f;
#pragma unroll
            for (int j = 0; j < 8; j++) v += sred[r][c][j];
            rr[c] = v;
        }
        float t1 = g_tconst[0], t2 = g_tconst[1], u = g_tconst[2];
        float a1 = 1.0f + rr[0];
        float s1 = a1 * rr[1] + t1;
        float a2 = a1 + s1;
        float s2 = a2 * rr[2] + t2;
        float a3 = a2 + s2;
        g_xdot[b0 + r] = a3 * rr[3] + u;
    }
}

// ---------------------------------------------------------------------------
// bf16 tensor-core GEMM + bias + relu, 2-stage cp.async pipeline.
// BM = WM*MT*16 = 128, BN = WN*NT*8.  256 threads (8 warps).
//   GEMM1: WM=2, WN=4, MT=4, NT=4 -> 128x128 tile
//   GEMM2/3: WM=4, WN=2, MT=2, NT=4 -> 128x64 tile
// ---------------------------------------------------------------------------
template<int WM, int WN, int MT, int NT>
__global__ __launch_bounds__(256) void k_gemm_bf16(
    const __nv_bfloat16* __restrict__ A,   // [M][K]
    const __nv_bfloat16* __restrict__ Bt,  // [N][K]
    const float* __restrict__ bias,        // [N]
    __nv_bfloat16* __restrict__ C,         // [M][N]
    int M, int N, int K)
{
    constexpr int BM = WM * MT * 16;       // 128
    constexpr int BN = WN * NT * 8;
    static_assert(BM == 128, "BM must be 128");

    __shared__ __align__(16) __nv_bfloat16 As[2][BM][40];
    __shared__ __align__(16) __nv_bfloat16 Bs[2][BN][40];

    const int tid  = threadIdx.x;
    const int warp = tid >> 5, lane = tid & 31;
    const int g = lane >> 2, t = lane & 3;
    const int wm = (warp % WM) * (MT * 16);
    const int wn = (warp / WM) * (NT * 8);
    const int bm0 = blockIdx.y * BM;
    const int bn0 = blockIdx.x * BN;

    float acc[MT][NT][4];
#pragma unroll
    for (int i = 0; i < MT; i++)
#pragma unroll
        for (int j = 0; j < NT; j++)
#pragma unroll
            for (int c = 0; c < 4; c++) acc[i][j][c] = 0.0f;

    const int r_  = tid >> 2;          // 0..63
    const int kp_ = (tid & 3) * 8;

    // stage loader: 16B cp.async per op
    auto load_stage = [&](int s, int k0) {
#pragma unroll
        for (int i = 0; i < BM / 64; i++) {
            int r = r_ + i * 64;
            CP16(smem_u32(&As[s][r][kp_]),
                 &A[(size_t)(bm0 + r) * K + k0 + kp_]);
        }
#pragma unroll
        for (int i = 0; i < BN / 64; i++) {
            int r = r_ + i * 64;
            CP16(smem_u32(&Bs[s][r][kp_]),
                 &Bt[(size_t)(bn0 + r) * K + k0 + kp_]);
        }
        CP_COMMIT();
    };

    const int niter = K >> 5;
    load_stage(0, 0);

    for (int it = 0; it < niter; it++) {
        const int buf = it & 1;
        if (it + 1 < niter) {
            load_stage(buf ^ 1, (it + 1) << 5);
            asm volatile("cp.async.wait_group 1;\n");
        } else {
            asm volatile("cp.async.wait_group 0;\n");
        }
        __syncthreads();

#pragma unroll
        for (int ks = 0; ks < 32; ks += 16) {
            uint32_t af[MT][4], bf[NT][2];
#pragma unroll
            for (int mt = 0; mt < MT; mt++) {
                int rm = wm + mt * 16 + g;
                af[mt][0] = *(const uint32_t*)&As[buf][rm][ks + 2 * t];
                af[mt][1] = *(const uint32_t*)&As[buf][rm + 8][ks + 2 * t];
                af[mt][2] = *(const uint32_t*)&As[buf][rm][ks + 2 * t + 8];
                af[mt][3] = *(const uint32_t*)&As[buf][rm + 8][ks + 2 * t + 8];
            }
#pragma unroll
            for (int nt = 0; nt < NT; nt++) {
                int rn = wn + nt * 8 + g;
                bf[nt][0] = *(const uint32_t*)&Bs[buf][rn][ks + 2 * t];
                bf[nt][1] = *(const uint32_t*)&Bs[buf][rn][ks + 2 * t + 8];
            }
#pragma unroll
            for (int mt = 0; mt < MT; mt++)
#pragma unroll
                for (int nt = 0; nt < NT; nt++) {
                    asm volatile(
                        "mma.sync.aligned.m16n8k16.row.col.f32.bf16.bf16.f32 "
                        "{%0,%1,%2,%3}, {%4,%5,%6,%7}, {%8,%9}, {%0,%1,%2,%3};\n"
                        : "+f"(acc[mt][nt][0]), "+f"(acc[mt][nt][1]),
                          "+f"(acc[mt][nt][2]), "+f"(acc[mt][nt][3])
                        : "r"(af[mt][0]), "r"(af[mt][1]), "r"(af[mt][2]), "r"(af[mt][3]),
                          "r"(bf[nt][0]), "r"(bf[nt][1]));
                }
        }
        __syncthreads();   // protect buf from being overwritten at it+2's issue
    }

#pragma unroll
    for (int mt = 0; mt < MT; mt++) {
        int row0 = bm0 + wm + mt * 16 + g;
#pragma unroll
        for (int nt = 0; nt < NT; nt++) {
            int col = bn0 + wn + nt * 8 + 2 * t;
            float b0v = bias[col], b1v = bias[col + 1];
            float v00 = fmaxf(acc[mt][nt][0] + b0v, 0.0f);
            float v01 = fmaxf(acc[mt][nt][1] + b1v, 0.0f);
            float v10 = fmaxf(acc[mt][nt][2] + b0v, 0.0f);
            float v11 = fmaxf(acc[mt][nt][3] + b1v, 0.0f);
            __nv_bfloat162 p0 = __floats2bfloat162_rn(v00, v01);
            __nv_bfloat162 p1 = __floats2bfloat162_rn(v10, v11);
            *(__nv_bfloat162*)&C[(size_t)row0 * N + col]       = p0;
            *(__nv_bfloat162*)&C[(size_t)(row0 + 8) * N + col] = p1;
        }
    }
}

// ---------------------------------------------------------------------------
// Head: logit = g_xdot[b] + h3[b] . out_w[D:D+256] + out_b; out = sigmoid.
// ---------------------------------------------------------------------------
__global__ __launch_bounds__(256) void k_head(
    const __nv_bfloat16* __restrict__ h3,
    const float* __restrict__ out_w,
    const float* __restrict__ out_b,
    float* __restrict__ out)
{
    const int b = blockIdx.x * 8 + (threadIdx.x >> 5);
    const int l = threadIdx.x & 31;
    float p = 0.0f;
#pragma unroll
    for (int j = 0; j < N3 / 32; j++) {
        int idx = l + j * 32;
        p += __bfloat162float(h3[b * N3 + idx]) * out_w[D_ + idx];
    }
#pragma unroll
    for (int o = 16; o > 0; o >>= 1) p += __shfl_xor_sync(0xffffffffu, p, o);
    if (l == 0) {
        float logit = g_xdot[b] + p + out_b[0];
        out[b] = 1.0f / (1.0f + expf(-logit));
    }
}

// ---------------------------------------------------------------------------
extern "C" void kernel_launch(void* const* d_in, const int* in_sizes, int n_in,
                              void* d_out, int out_size)
{
    const int*   ids     = (const int*)  d_in[0];
    const float* emb     = (const float*)d_in[1];
    const float* cross_w = (const float*)d_in[2];
    const float* cross_b = (const float*)d_in[3];
    const float* w1      = (const float*)d_in[4];
    const float* b1      = (const float*)d_in[5];
    const float* w2      = (const float*)d_in[6];
    const float* b2      = (const float*)d_in[7];
    const float* w3      = (const float*)d_in[8];
    const float* b3      = (const float*)d_in[9];
    const float* out_w   = (const float*)d_in[10];
    const float* out_b   = (const float*)d_in[11];
    float* out = (float*)d_out;

    __nv_bfloat16 *x0b, *h1b, *h2b, *h3b, *w1t, *w2t, *w3t;
    cudaGetSymbolAddress((void**)&x0b, g_x0b);
    cudaGetSymbolAddress((void**)&h1b, g_h1b);
    cudaGetSymbolAddress((void**)&h2b, g_h2b);
    cudaGetSymbolAddress((void**)&h3b, g_h3b);
    cudaGetSymbolAddress((void**)&w1t, g_w1t);
    cudaGetSymbolAddress((void**)&w2t, g_w2t);
    cudaGetSymbolAddress((void**)&w3t, g_w3t);

    // 0) all prep in one launch (transposes + cross constants)
    k_prep<<<PREP_BLOCKS, 256>>>(w1, w2, w3, w1t, w2t, w3t,
                                 cross_w, cross_b, out_w);

    // 1) fused gather + collapsed cross (fp32 exact path), 2 rows/block
    k_gather_cross<<<B_ / RPB, 256>>>(ids, emb, cross_w, out_w);

    // 2) deep tower on tensor cores (bf16 in, fp32 accum), cp.async pipeline
    k_gemm_bf16<2, 4, 4, 4><<<dim3(N1 / 128, B_ / 128), 256>>>(x0b, w1t, b1, h1b, B_, N1, D_);
    k_gemm_bf16<4, 2, 2, 4><<<dim3(N2 /  64, B_ / 128), 256>>>(h1b, w2t, b2, h2b, B_, N2, N1);
    k_gemm_bf16<4, 2, 2, 4><<<dim3(N3 /  64, B_ / 128), 256>>>(h2b, w3t, b3, h3b, B_, N3, N2);

    // 3) head
    k_head<<<B_ / 8, 256>>>(h3b, out_w, out_b, out);
}

// round 11
// speedup vs baseline: 6.2698x; 1.1527x over previous
#include <cuda_runtime.h>
#include <cuda_bf16.h>
#include <math.h>
#include <cstdint>

// Problem constants
#define B_  4096
#define F_  26
#define E_  64
#define D_  1664          // F_*E_
#define NV4 (D_ / 4)
#define N1  1024
#define N2  512
#define N3  256

// Scratch (no cudaMalloc allowed)
__device__ __nv_bfloat16 g_x0b[B_ * D_];
__device__ float        g_xdot[B_];
__device__ float        g_tconst[3];
__device__ __nv_bfloat16 g_h1b[B_ * N1];
__device__ __nv_bfloat16 g_h2b[B_ * N2];
__device__ __nv_bfloat16 g_h3b[B_ * N3];
__device__ __nv_bfloat16 g_w1t[N1 * D_];
__device__ __nv_bfloat16 g_w2t[N2 * N1];
__device__ __nv_bfloat16 g_w3t[N3 * N2];

__device__ __forceinline__ uint32_t smem_u32(const void* p) {
    return (uint32_t)__cvta_generic_to_shared(p);
}
#define CP16(dst, src) \
    asm volatile("cp.async.ca.shared.global [%0], [%1], 16;\n" :: "r"(dst), "l"(src))
#define CP_COMMIT() asm volatile("cp.async.commit_group;\n")

__device__ __forceinline__ void ldsm_x4(uint32_t& r0, uint32_t& r1,
                                        uint32_t& r2, uint32_t& r3, uint32_t a) {
    asm volatile("ldmatrix.sync.aligned.m8n8.x4.shared.b16 {%0,%1,%2,%3}, [%4];\n"
                 : "=r"(r0), "=r"(r1), "=r"(r2), "=r"(r3) : "r"(a));
}

// ---------------------------------------------------------------------------
// One launch: all three weight transposes (fp32 [K][N] -> bf16 [N][K]) plus
// the bias-derived constant scalars of the collapsed cross net.
// ---------------------------------------------------------------------------
#define T1_TILES ((N1/32)*(D_/32))             // 1664
#define T2_TILES ((N2/32)*(N1/32))             // 512
#define T3_TILES ((N3/32)*(N2/32))             // 128
#define PREP_BLOCKS (T1_TILES + T2_TILES + T3_TILES + 1)

__global__ __launch_bounds__(256) void k_prep(
    const float* __restrict__ w1, const float* __restrict__ w2,
    const float* __restrict__ w3,
    __nv_bfloat16* __restrict__ w1t, __nv_bfloat16* __restrict__ w2t,
    __nv_bfloat16* __restrict__ w3t,
    const float* __restrict__ cross_w, const float* __restrict__ cross_b,
    const float* __restrict__ out_w)
{
    const int bid = blockIdx.x;
    const int tid = threadIdx.x;

    if (bid == T1_TILES + T2_TILES + T3_TILES) {
        __shared__ float sred[3][8];
        float a1 = 0.f, a2 = 0.f, a3 = 0.f;
        for (int d = tid; d < D_; d += 256) {
            float c0 = cross_b[d];
            float c01 = c0 + cross_b[D_ + d];
            float c012 = c01 + cross_b[2 * D_ + d];
            a1 += c0   * cross_w[D_ + d];
            a2 += c01  * cross_w[2 * D_ + d];
            a3 += c012 * out_w[d];
        }
#pragma unroll
        for (int o = 16; o > 0; o >>= 1) {
            a1 += __shfl_xor_sync(0xffffffffu, a1, o);
            a2 += __shfl_xor_sync(0xffffffffu, a2, o);
            a3 += __shfl_xor_sync(0xffffffffu, a3, o);
        }
        int w = tid >> 5, l = tid & 31;
        if (l == 0) { sred[0][w] = a1; sred[1][w] = a2; sred[2][w] = a3; }
        __syncthreads();
        if (tid < 3) {
            float v = 0.f;
#pragma unroll
            for (int j = 0; j < 8; j++) v += sred[tid][j];
            g_tconst[tid] = v;
        }
        return;
    }

    const float* W; __nv_bfloat16* Wt; int K, N, tile;
    if (bid < T1_TILES)                 { W = w1; Wt = w1t; K = D_; N = N1; tile = bid; }
    else if (bid < T1_TILES + T2_TILES) { W = w2; Wt = w2t; K = N1; N = N2; tile = bid - T1_TILES; }
    else                                { W = w3; Wt = w3t; K = N2; N = N3; tile = bid - T1_TILES - T2_TILES; }

    __shared__ float s[32][33];
    const int tilesN = N / 32;
    const int n0 = (tile % tilesN) * 32, k0 = (tile / tilesN) * 32;
    const int tx = tid & 31, ty = tid >> 5;
#pragma unroll
    for (int i = 0; i < 32; i += 8)
        s[ty + i][tx] = W[(size_t)(k0 + ty + i) * N + n0 + tx];
    __syncthreads();
#pragma unroll
    for (int i = 0; i < 32; i += 8)
        Wt[(size_t)(n0 + ty + i) * K + k0 + tx] = __float2bfloat16(s[tx][ty + i]);
}

// ---------------------------------------------------------------------------
// Fused gather + collapsed cross + head partial, 2 rows per block.
// ---------------------------------------------------------------------------
#define RPB 2
__global__ __launch_bounds__(256) void k_gather_cross(
    const int* __restrict__ ids,
    const float* __restrict__ emb,
    const float* __restrict__ cross_w,
    const float* __restrict__ out_w)
{
    const int b0 = blockIdx.x * RPB;
    const int tid = threadIdx.x;

    __shared__ int sid[RPB][F_];
    __shared__ float sred[RPB][4][8];

    if (tid < RPB * F_) {
        int r = tid / F_, f = tid % F_;
        sid[r][f] = ids[(b0 + r) * F_ + f];
    }
    __syncthreads();

    float q[RPB][4];
#pragma unroll
    for (int r = 0; r < RPB; r++)
#pragma unroll
        for (int c = 0; c < 4; c++) q[r][c] = 0.f;

    for (int v4 = tid; v4 < NV4; v4 += 256) {
        int f = v4 >> 4;
        int e4 = (v4 & 15) << 2;
        int d = v4 << 2;

        float4 w0 = *(const float4*)&cross_w[d];
        float4 w1 = *(const float4*)&cross_w[D_ + d];
        float4 w2 = *(const float4*)&cross_w[2 * D_ + d];
        float4 wo = *(const float4*)&out_w[d];

#pragma unroll
        for (int r = 0; r < RPB; r++) {
            int row = sid[r][f];
            float4 v = *(const float4*)&emb[(size_t)row * E_ + e4];
            q[r][0] += v.x * w0.x + v.y * w0.y + v.z * w0.z + v.w * w0.w;
            q[r][1] += v.x * w1.x + v.y * w1.y + v.z * w1.z + v.w * w1.w;
            q[r][2] += v.x * w2.x + v.y * w2.y + v.z * w2.z + v.w * w2.w;
            q[r][3] += v.x * wo.x + v.y * wo.y + v.z * wo.z + v.w * wo.w;

            __nv_bfloat162 p0 = __floats2bfloat162_rn(v.x, v.y);
            __nv_bfloat162 p1 = __floats2bfloat162_rn(v.z, v.w);
            uint2 pk;
            pk.x = *(uint32_t*)&p0;
            pk.y = *(uint32_t*)&p1;
            *(uint2*)&g_x0b[(size_t)(b0 + r) * D_ + d] = pk;
        }
    }

#pragma unroll
    for (int r = 0; r < RPB; r++)
#pragma unroll
        for (int c = 0; c < 4; c++)
#pragma unroll
            for (int o = 16; o > 0; o >>= 1)
                q[r][c] += __shfl_xor_sync(0xffffffffu, q[r][c], o);

    int w = tid >> 5, l = tid & 31;
    if (l == 0)
#pragma unroll
        for (int r = 0; r < RPB; r++)
#pragma unroll
            for (int c = 0; c < 4; c++) sred[r][c][w] = q[r][c];
    __syncthreads();
    if (tid < RPB) {
        int r = tid;
        float rr[4];
#pragma unroll
        for (int c = 0; c < 4; c++) {
            float v = 0.f;
#pragma unroll
            for (int j = 0; j < 8; j++) v += sred[r][c][j];
            rr[c] = v;
        }
        float t1 = g_tconst[0], t2 = g_tconst[1], u = g_tconst[2];
        float a1 = 1.0f + rr[0];
        float s1 = a1 * rr[1] + t1;
        float a2 = a1 + s1;
        float s2 = a2 * rr[2] + t2;
        float a3 = a2 + s2;
        g_xdot[b0 + r] = a3 * rr[3] + u;
    }
}

// ---------------------------------------------------------------------------
// bf16 tensor-core GEMM + bias + relu.
// 3-stage cp.async circular pipeline, ONE __syncthreads per BK=32 slab,
// ldmatrix.x4 fragment loads. BM = WM*MT*16, BN = WN*NT*8. 256 threads.
// Dynamic smem: 3*(BM+BN)*40*2 bytes.
// ---------------------------------------------------------------------------
template<int WM, int WN, int MT, int NT>
__global__ __launch_bounds__(256) void k_gemm_bf16(
    const __nv_bfloat16* __restrict__ A,   // [M][K]
    const __nv_bfloat16* __restrict__ Bt,  // [N][K]
    const float* __restrict__ bias,        // [N]
    __nv_bfloat16* __restrict__ C,         // [M][N]
    int M, int N, int K)
{
    constexpr int BM = WM * MT * 16;
    constexpr int BN = WN * NT * 8;
    constexpr int S  = 3;
    static_assert(NT % 2 == 0, "NT must be even for paired ldmatrix");
    static_assert(BM % 64 == 0 && BN % 64 == 0, "loader assumes 64-row groups");

    extern __shared__ __align__(16) unsigned char smem_raw[];
    __nv_bfloat16 (*As)[40] = reinterpret_cast<__nv_bfloat16 (*)[40]>(smem_raw);
    __nv_bfloat16 (*Bs)[40] =
        reinterpret_cast<__nv_bfloat16 (*)[40]>(smem_raw + (size_t)S * BM * 40 * 2);

    const int tid  = threadIdx.x;
    const int warp = tid >> 5, lane = tid & 31;
    const int g = lane >> 2, t = lane & 3;
    const int wm = (warp % WM) * (MT * 16);
    const int wn = (warp / WM) * (NT * 8);
    const int bm0 = blockIdx.y * BM;
    const int bn0 = blockIdx.x * BN;

    // ldmatrix lane address components
    const int a_row = wm + (lane & 15);            // + mt*16 + buf*BM
    const int a_col = (lane >> 4) << 3;            // + ks
    const int b_row = wn + (lane & 7) + ((lane >> 4) << 3);  // + pair*16 + buf*BN
    const int b_col = ((lane >> 3) & 1) << 3;      // + ks

    float acc[MT][NT][4];
#pragma unroll
    for (int i = 0; i < MT; i++)
#pragma unroll
        for (int j = 0; j < NT; j++)
#pragma unroll
            for (int c = 0; c < 4; c++) acc[i][j][c] = 0.0f;

    const int r_  = tid >> 2;          // 0..63
    const int kp_ = (tid & 3) * 8;

    auto load_stage = [&](int s, int k0) {
#pragma unroll
        for (int i = 0; i < BM / 64; i++) {
            int r = r_ + i * 64;
            CP16(smem_u32(&As[s * BM + r][kp_]),
                 &A[(size_t)(bm0 + r) * K + k0 + kp_]);
        }
#pragma unroll
        for (int i = 0; i < BN / 64; i++) {
            int r = r_ + i * 64;
            CP16(smem_u32(&Bs[s * BN + r][kp_]),
                 &Bt[(size_t)(bn0 + r) * K + k0 + kp_]);
        }
        CP_COMMIT();
    };

    const int niter = K >> 5;
    load_stage(0, 0);
    if (niter > 1) load_stage(1, 32);

    for (int it = 0; it < niter; it++) {
        const int buf = it % S;
        if (it + 1 < niter) asm volatile("cp.async.wait_group 1;\n");
        else                asm volatile("cp.async.wait_group 0;\n");
        __syncthreads();

        if (it + 2 < niter) load_stage((it + 2) % S, (it + 2) << 5);

#pragma unroll
        for (int ks = 0; ks < 32; ks += 16) {
            uint32_t af[MT][4], bf[NT][2];
#pragma unroll
            for (int mt = 0; mt < MT; mt++)
                ldsm_x4(af[mt][0], af[mt][1], af[mt][2], af[mt][3],
                        smem_u32(&As[buf * BM + a_row + mt * 16][a_col + ks]));
#pragma unroll
            for (int p = 0; p < NT / 2; p++)
                ldsm_x4(bf[2 * p][0], bf[2 * p][1], bf[2 * p + 1][0], bf[2 * p + 1][1],
                        smem_u32(&Bs[buf * BN + b_row + p * 16][b_col + ks]));
#pragma unroll
            for (int mt = 0; mt < MT; mt++)
#pragma unroll
                for (int nt = 0; nt < NT; nt++) {
                    asm volatile(
                        "mma.sync.aligned.m16n8k16.row.col.f32.bf16.bf16.f32 "
                        "{%0,%1,%2,%3}, {%4,%5,%6,%7}, {%8,%9}, {%0,%1,%2,%3};\n"
                        : "+f"(acc[mt][nt][0]), "+f"(acc[mt][nt][1]),
                          "+f"(acc[mt][nt][2]), "+f"(acc[mt][nt][3])
                        : "r"(af[mt][0]), "r"(af[mt][1]), "r"(af[mt][2]), "r"(af[mt][3]),
                          "r"(bf[nt][0]), "r"(bf[nt][1]));
                }
        }
    }

#pragma unroll
    for (int mt = 0; mt < MT; mt++) {
        int row0 = bm0 + wm + mt * 16 + g;
#pragma unroll
        for (int nt = 0; nt < NT; nt++) {
            int col = bn0 + wn + nt * 8 + 2 * t;
            float b0v = bias[col], b1v = bias[col + 1];
            float v00 = fmaxf(acc[mt][nt][0] + b0v, 0.0f);
            float v01 = fmaxf(acc[mt][nt][1] + b1v, 0.0f);
            float v10 = fmaxf(acc[mt][nt][2] + b0v, 0.0f);
            float v11 = fmaxf(acc[mt][nt][3] + b1v, 0.0f);
            __nv_bfloat162 p0 = __floats2bfloat162_rn(v00, v01);
            __nv_bfloat162 p1 = __floats2bfloat162_rn(v10, v11);
            *(__nv_bfloat162*)&C[(size_t)row0 * N + col]       = p0;
            *(__nv_bfloat162*)&C[(size_t)(row0 + 8) * N + col] = p1;
        }
    }
}

// ---------------------------------------------------------------------------
// Head: logit = g_xdot[b] + h3[b] . out_w[D:D+256] + out_b; out = sigmoid.
// ---------------------------------------------------------------------------
__global__ __launch_bounds__(256) void k_head(
    const __nv_bfloat16* __restrict__ h3,
    const float* __restrict__ out_w,
    const float* __restrict__ out_b,
    float* __restrict__ out)
{
    const int b = blockIdx.x * 8 + (threadIdx.x >> 5);
    const int l = threadIdx.x & 31;
    float p = 0.0f;
#pragma unroll
    for (int j = 0; j < N3 / 32; j++) {
        int idx = l + j * 32;
        p += __bfloat162float(h3[b * N3 + idx]) * out_w[D_ + idx];
    }
#pragma unroll
    for (int o = 16; o > 0; o >>= 1) p += __shfl_xor_sync(0xffffffffu, p, o);
    if (l == 0) {
        float logit = g_xdot[b] + p + out_b[0];
        out[b] = 1.0f / (1.0f + expf(-logit));
    }
}

// ---------------------------------------------------------------------------
extern "C" void kernel_launch(void* const* d_in, const int* in_sizes, int n_in,
                              void* d_out, int out_size)
{
    const int*   ids     = (const int*)  d_in[0];
    const float* emb     = (const float*)d_in[1];
    const float* cross_w = (const float*)d_in[2];
    const float* cross_b = (const float*)d_in[3];
    const float* w1      = (const float*)d_in[4];
    const float* b1      = (const float*)d_in[5];
    const float* w2      = (const float*)d_in[6];
    const float* b2      = (const float*)d_in[7];
    const float* w3      = (const float*)d_in[8];
    const float* b3      = (const float*)d_in[9];
    const float* out_w   = (const float*)d_in[10];
    const float* out_b   = (const float*)d_in[11];
    float* out = (float*)d_out;

    __nv_bfloat16 *x0b, *h1b, *h2b, *h3b, *w1t, *w2t, *w3t;
    cudaGetSymbolAddress((void**)&x0b, g_x0b);
    cudaGetSymbolAddress((void**)&h1b, g_h1b);
    cudaGetSymbolAddress((void**)&h2b, g_h2b);
    cudaGetSymbolAddress((void**)&h3b, g_h3b);
    cudaGetSymbolAddress((void**)&w1t, g_w1t);
    cudaGetSymbolAddress((void**)&w2t, g_w2t);
    cudaGetSymbolAddress((void**)&w3t, g_w3t);

    // smem sizes: 3 stages * (BM+BN) rows * 40 bf16
    const int smem1 = 3 * (128 + 128) * 40 * 2;   // 61440 (needs opt-in)
    const int smem2 = 3 * (128 +  64) * 40 * 2;   // 46080
    const int smem3 = 3 * ( 64 +  64) * 40 * 2;   // 30720
    cudaFuncSetAttribute((const void*)k_gemm_bf16<2, 4, 4, 4>,
                         cudaFuncAttributeMaxDynamicSharedMemorySize, smem1);

    // 0) all prep in one launch (transposes + cross constants)
    k_prep<<<PREP_BLOCKS, 256>>>(w1, w2, w3, w1t, w2t, w3t,
                                 cross_w, cross_b, out_w);

    // 1) fused gather + collapsed cross (fp32 exact path)
    k_gather_cross<<<B_ / RPB, 256>>>(ids, emb, cross_w, out_w);

    // 2) deep tower on tensor cores
    k_gemm_bf16<2, 4, 4, 4><<<dim3(N1 / 128, B_ / 128), 256, smem1>>>(x0b, w1t, b1, h1b, B_, N1, D_);
    k_gemm_bf16<4, 2, 2, 4><<<dim3(N2 /  64, B_ / 128), 256, smem2>>>(h1b, w2t, b2, h2b, B_, N2, N1);
    k_gemm_bf16<2, 4, 2, 2><<<dim3(N3 /  64, B_ /  64), 256, smem3>>>(h2b, w3t, b3, h3b, B_, N3, N2);

    // 3) head
    k_head<<<B_ / 8, 256>>>(h3b, out_w, out_b, out);
}